// round 9
// baseline (speedup 1.0000x reference)
#include <cuda_runtime.h>
#include <stdint.h>

#define N_TOK 8192
#define NE    16384
#define EDIM  256
#define NBLK  (NE / 128)            // 128 column blocks

#define Z_ELEMS   (N_TOK * EDIM)    // 2,097,152 (z input)
#define EMB_ELEMS (NE * EDIM)       // 4,194,304 (emb input)
#define ZQ_ELEMS  (N_TOK * EDIM)    // 2,097,152 (z_q output: [8,256,32,32])

typedef unsigned long long u64;

// ---- scratch (alloc-free: __device__ globals) ----
__device__ __align__(16) float g_zn[N_TOK * EDIM];   // 8 MB  normalized tokens
__device__ __align__(16) float g_en[NE * EDIM];      // 16 MB normalized codebook
__device__ float g_e2[NE];                           // ||en_j||^2 (fp32)
__device__ u64 g_top1[N_TOK * NBLK];                 // per (token, col-block) best
__device__ u64 g_top2[N_TOK * NBLK];                 // per (token, col-block) 2nd
__device__ int g_idx[N_TOK];                         // final winner
__device__ float g_loss_part[N_TOK];

// monotone map float -> uint32 (f1<f2 => key(f1)<key(f2))
__device__ __forceinline__ unsigned int fkey(float f) {
    unsigned int u = __float_as_uint(f);
    return u ^ ((unsigned int)((int)u >> 31) | 0x80000000u);
}

// ---------------------------------------------------------------------------
// Kernel 1: normalize z tokens. z is [B=8][C=256][H=32][W=32]; token n=(b,h,w).
__global__ void knorm_z(const float* __restrict__ z) {
    __shared__ float tile[32][EDIM + 1];
    int blk = blockIdx.x;                 // 0..255 = (b,h)
    int b = blk >> 5, h = blk & 31;
    int tid = threadIdx.x;
    const float* zb = z + (size_t)b * (EDIM * 1024) + h * 32;
    for (int i = tid; i < 32 * EDIM; i += 256) {
        int c = i >> 5, w = i & 31;
        tile[w][c] = zb[c * 1024 + w];
    }
    __syncthreads();
    int warp = tid >> 5, lane = tid & 31;
    for (int s = 0; s < 4; s++) {
        int w = warp * 4 + s;
        float acc = 0.f;
        #pragma unroll
        for (int c = lane; c < EDIM; c += 32) { float v = tile[w][c]; acc += v * v; }
        #pragma unroll
        for (int o = 16; o > 0; o >>= 1) acc += __shfl_xor_sync(0xFFFFFFFFu, acc, o);
        float den = fmaxf(sqrtf(acc), 1e-12f);
        int n = b * 1024 + h * 32 + w;
        #pragma unroll
        for (int c = lane; c < EDIM; c += 32)
            g_zn[(size_t)n * EDIM + c] = tile[w][c] / den;
    }
}

// ---------------------------------------------------------------------------
// Kernel 2: normalize codebook rows; e2 = ||en_j||^2.
__global__ void knorm_e(const float* __restrict__ emb) {
    int j = blockIdx.x, tid = threadIdx.x;
    float v = emb[(size_t)j * EDIM + tid];
    __shared__ float sm[8];
    float s = v * v;
    #pragma unroll
    for (int o = 16; o > 0; o >>= 1) s += __shfl_xor_sync(0xFFFFFFFFu, s, o);
    if ((tid & 31) == 0) sm[tid >> 5] = s;
    __syncthreads();
    float tot = sm[0] + sm[1] + sm[2] + sm[3] + sm[4] + sm[5] + sm[6] + sm[7];
    float den = fmaxf(sqrtf(tot), 1e-12f);
    float e = v / den;
    g_en[(size_t)j * EDIM + tid] = e;
    __syncthreads();
    float s2 = e * e;
    #pragma unroll
    for (int o = 16; o > 0; o >>= 1) s2 += __shfl_xor_sync(0xFFFFFFFFu, s2, o);
    if ((tid & 31) == 0) sm[tid >> 5] = s2;
    __syncthreads();
    if (tid == 0)
        g_e2[j] = sm[0] + sm[1] + sm[2] + sm[3] + sm[4] + sm[5] + sm[6] + sm[7];
}

// ---------------------------------------------------------------------------
// Kernel 3: fp32 GEMM + per-block exact top-2.  score = 2*dot - e2.
__global__ void __launch_bounds__(256) kgemm_top2() {
    __shared__ __align__(16) unsigned char sbuf[32768];  // As+Bs (16896) | red1+red2 (32768)
    float (*As)[132] = (float(*)[132])sbuf;              // [16][132]
    float (*Bs)[132] = (float(*)[132])(sbuf + 8448);     // [16][132]
    __shared__ float e2s[128];

    int tid = threadIdx.x;
    int tx = tid & 15, ty = tid >> 4;
    int m0 = blockIdx.y * 128, n0 = blockIdx.x * 128;
    if (tid < 128) e2s[tid] = g_e2[n0 + tid];

    float acc[8][8];
    #pragma unroll
    for (int i = 0; i < 8; i++)
        #pragma unroll
        for (int j = 0; j < 8; j++) acc[i][j] = 0.f;

    const float* Ab = g_zn + (size_t)m0 * EDIM;
    const float* Bb = g_en + (size_t)n0 * EDIM;

    int r0 = tid >> 2,         c0 = (tid & 3) * 4;
    int r1 = (256 + tid) >> 2, c1 = ((256 + tid) & 3) * 4;

    float4 va0 = *(const float4*)(Ab + (size_t)r0 * EDIM + c0);
    float4 va1 = *(const float4*)(Ab + (size_t)r1 * EDIM + c1);
    float4 vb0 = *(const float4*)(Bb + (size_t)r0 * EDIM + c0);
    float4 vb1 = *(const float4*)(Bb + (size_t)r1 * EDIM + c1);

    for (int k0 = 0; k0 < EDIM; k0 += 16) {
        As[c0 + 0][r0] = va0.x; As[c0 + 1][r0] = va0.y; As[c0 + 2][r0] = va0.z; As[c0 + 3][r0] = va0.w;
        As[c1 + 0][r1] = va1.x; As[c1 + 1][r1] = va1.y; As[c1 + 2][r1] = va1.z; As[c1 + 3][r1] = va1.w;
        Bs[c0 + 0][r0] = vb0.x; Bs[c0 + 1][r0] = vb0.y; Bs[c0 + 2][r0] = vb0.z; Bs[c0 + 3][r0] = vb0.w;
        Bs[c1 + 0][r1] = vb1.x; Bs[c1 + 1][r1] = vb1.y; Bs[c1 + 2][r1] = vb1.z; Bs[c1 + 3][r1] = vb1.w;
        __syncthreads();

        int kn = k0 + 16;
        if (kn < EDIM) {
            va0 = *(const float4*)(Ab + (size_t)r0 * EDIM + kn + c0);
            va1 = *(const float4*)(Ab + (size_t)r1 * EDIM + kn + c1);
            vb0 = *(const float4*)(Bb + (size_t)r0 * EDIM + kn + c0);
            vb1 = *(const float4*)(Bb + (size_t)r1 * EDIM + kn + c1);
        }

        #pragma unroll
        for (int kk = 0; kk < 16; kk++) {
            float4 a0 = *(const float4*)&As[kk][ty * 4];
            float4 a1 = *(const float4*)&As[kk][64 + ty * 4];
            float4 b0 = *(const float4*)&Bs[kk][tx * 4];
            float4 b1 = *(const float4*)&Bs[kk][64 + tx * 4];
            float a[8] = {a0.x, a0.y, a0.z, a0.w, a1.x, a1.y, a1.z, a1.w};
            float bv[8] = {b0.x, b0.y, b0.z, b0.w, b1.x, b1.y, b1.z, b1.w};
            #pragma unroll
            for (int i = 0; i < 8; i++)
                #pragma unroll
                for (int j = 0; j < 8; j++)
                    acc[i][j] = fmaf(a[i], bv[j], acc[i][j]);
        }
        __syncthreads();   // As/Bs dead after last iter -> safe to alias below
    }

    // ---- epilogue: per-thread top-2, per-row top-2, store per-block ----
    u64* red1 = (u64*)sbuf;            // [128][16]
    u64* red2 = red1 + 128 * 16;       // [128][16]

    #pragma unroll
    for (int i = 0; i < 8; i++) {
        int mi = (i < 4) ? (ty * 4 + i) : (64 + ty * 4 + i - 4);
        u64 p1 = 0ULL, p2 = 0ULL;
        #pragma unroll
        for (int j = 0; j < 8; j++) {
            int nl = (j < 4) ? (tx * 4 + j) : (64 + tx * 4 + j - 4);
            float sc = 2.0f * acc[i][j] - e2s[nl];
            u64 p = ((u64)fkey(sc) << 32) | (unsigned int)(~(unsigned int)(n0 + nl));
            if (p > p1) { p2 = p1; p1 = p; } else if (p > p2) { p2 = p; }
        }
        red1[mi * 16 + tx] = p1;
        red2[mi * 16 + tx] = p2;
    }
    __syncthreads();
    if (tid < 128) {
        u64 b1 = 0ULL, b2 = 0ULL;
        #pragma unroll
        for (int t = 0; t < 16; t++) {
            u64 u1 = red1[tid * 16 + t], u2 = red2[tid * 16 + t];
            if (u1 > b1) { b2 = (b1 > u2) ? b1 : u2; b1 = u1; }
            else if (u1 > b2) { b2 = u1; }
        }
        size_t o = (size_t)(m0 + tid) * NBLK + blockIdx.x;
        g_top1[o] = b1;
        g_top2[o] = b2;
    }
}

// ---------------------------------------------------------------------------
// Kernel 4: merge block top-2 pairs per token; fp64 rescore of the 2 finalists.
__global__ void kpick() {
    int tid = threadIdx.x;
    int warp = tid >> 5, lane = tid & 31;
    int n = blockIdx.x * 8 + warp;

    u64 b1 = 0ULL, b2 = 0ULL;
    #pragma unroll
    for (int t = 0; t < 4; t++) {
        size_t o = (size_t)n * NBLK + lane * 4 + t;
        u64 u1 = g_top1[o], u2 = g_top2[o];
        if (u1 > b1) { b2 = (b1 > u2) ? b1 : u2; b1 = u1; }
        else if (u1 > b2) { b2 = u1; }
    }
    #pragma unroll
    for (int o = 16; o > 0; o >>= 1) {
        u64 u1 = __shfl_xor_sync(0xFFFFFFFFu, b1, o);
        u64 u2 = __shfl_xor_sync(0xFFFFFFFFu, b2, o);
        if (u1 > b1) { b2 = (b1 > u2) ? b1 : u2; b1 = u1; }
        else if (u1 > b2) { b2 = u1; }
    }
    int j1 = (int)(~(unsigned int)b1);
    int j2 = (int)(~(unsigned int)b2);

    // fp64 rescore: d = ||en||^2 - 2*zn.en  (z2 constant per token)
    const float* zr  = g_zn + (size_t)n * EDIM;
    const float* e1r = g_en + (size_t)j1 * EDIM;
    const float* e2r = g_en + (size_t)j2 * EDIM;
    double s1 = 0.0, s2 = 0.0, q1 = 0.0, q2 = 0.0;
    #pragma unroll
    for (int t = 0; t < 8; t++) {
        int c = lane * 8 + t;
        double a  = (double)zr[c];
        double x1 = (double)e1r[c];
        double x2 = (double)e2r[c];
        s1 += a * x1; q1 += x1 * x1;
        s2 += a * x2; q2 += x2 * x2;
    }
    #pragma unroll
    for (int o = 16; o > 0; o >>= 1) {
        s1 += __shfl_xor_sync(0xFFFFFFFFu, s1, o);
        s2 += __shfl_xor_sync(0xFFFFFFFFu, s2, o);
        q1 += __shfl_xor_sync(0xFFFFFFFFu, q1, o);
        q2 += __shfl_xor_sync(0xFFFFFFFFu, q2, o);
    }
    if (lane == 0) {
        double d1 = q1 - 2.0 * s1;
        double d2 = q2 - 2.0 * s2;
        int win = (d2 < d1 || (d2 == d1 && j2 < j1)) ? j2 : j1;
        g_idx[n] = win;
    }
}

// ---------------------------------------------------------------------------
// Kernel 5: gather z_q = emb[idx] (raw weights), outputs, loss partials.
__global__ void kgather(const float* __restrict__ emb,
                        float* __restrict__ out_zq,
                        float* __restrict__ out_idx, int has_idx) {
    int n = blockIdx.x, c = threadIdx.x;
    int j = g_idx[n];
    float q = emb[(size_t)j * EDIM + c];
    float zv = g_zn[(size_t)n * EDIM + c];
    float d = q - zv;
    __shared__ float sm[8];
    float s = d * d;
    #pragma unroll
    for (int o = 16; o > 0; o >>= 1) s += __shfl_xor_sync(0xFFFFFFFFu, s, o);
    if ((c & 31) == 0) sm[c >> 5] = s;
    __syncthreads();
    if (c == 0)
        g_loss_part[n] = sm[0] + sm[1] + sm[2] + sm[3] + sm[4] + sm[5] + sm[6] + sm[7];
    // output layout [b][c][h][w]: index = b*256*1024 + c*1024 + (h*32+w)
    int b = n >> 10, p2 = n & 1023;
    out_zq[(size_t)b * (EDIM * 1024) + (size_t)c * 1024 + p2] = q;
    if (c == 0 && has_idx) out_idx[n] = (float)j;
}

// ---------------------------------------------------------------------------
// Kernel 6: loss = 2.25 * mean(sq diff), deterministic fp64 reduction.
__global__ void kloss(float* __restrict__ out_loss) {
    int tid = threadIdx.x;
    double s = 0.0;
    for (int i = tid; i < N_TOK; i += 256) s += (double)g_loss_part[i];
    __shared__ double sm[8];
    #pragma unroll
    for (int o = 16; o > 0; o >>= 1) s += __shfl_xor_sync(0xFFFFFFFFu, s, o);
    if ((tid & 31) == 0) sm[tid >> 5] = s;
    __syncthreads();
    if (tid == 0) {
        double tot = sm[0] + sm[1] + sm[2] + sm[3] + sm[4] + sm[5] + sm[6] + sm[7];
        *out_loss = (float)(2.25 * tot / (double)((size_t)N_TOK * EDIM));
    }
}

// ---------------------------------------------------------------------------
extern "C" void kernel_launch(void* const* d_in, const int* in_sizes, int n_in,
                              void* d_out, int out_size) {
    const float* z   = (const float*)d_in[0];
    const float* emb = (const float*)d_in[n_in > 1 ? 1 : 0];
    for (int i = 0; i < n_in; i++) {
        long long sz = in_sizes[i];
        if (sz == Z_ELEMS)   z   = (const float*)d_in[i];
        if (sz == EMB_ELEMS) emb = (const float*)d_in[i];
    }

    // Output layout: z_q [2,097,152] | idx [8,192] | loss [1]  (total 2,105,345)
    float* out = (float*)d_out;
    float* out_zq = out;
    int has_idx  = out_size >= ZQ_ELEMS + N_TOK;
    int has_loss = out_size >= ZQ_ELEMS + N_TOK + 1;
    float* out_idx  = out + ZQ_ELEMS;
    float* out_loss = out + ZQ_ELEMS + N_TOK;

    knorm_z<<<256, 256>>>(z);
    knorm_e<<<NE, 256>>>(emb);
    dim3 g(NBLK, N_TOK / 128);
    kgemm_top2<<<g, 256>>>();
    kpick<<<N_TOK / 8, 256>>>();
    kgather<<<N_TOK, 256>>>(emb, out_zq, has_idx ? out_idx : (float*)0, has_idx);
    if (has_loss) kloss<<<1, 256>>>(out_loss);
}

// round 11
// speedup vs baseline: 2.8245x; 2.8245x over previous
#include <cuda_runtime.h>
#include <cuda_bf16.h>
#include <stdint.h>

#define N_TOK 8192
#define NE    16384
#define EDIM  256
#define NTILE 128                    // codes per iteration
#define NHALF (NE / 2)               // codes per CTA (N-split by 2)
#define NIT   (NHALF / NTILE)        // 64 iterations
#define ZQ_ELEMS  (N_TOK * EDIM)     // 2,097,152
#define Z_ELEMS   (N_TOK * EDIM)
#define EMB_ELEMS (NE * EDIM)

typedef unsigned long long u64;

// ---- scratch (alloc-free: __device__ globals) ----
__device__ __align__(16) float g_zn[N_TOK * EDIM];            // fp32 normalized tokens
__device__ __align__(16) float g_en[NE * EDIM];               // fp32 normalized codebook
__device__ __align__(16) __nv_bfloat16 g_zn16[N_TOK * EDIM];  // bf16 tokens (MMA A)
__device__ __align__(16) __nv_bfloat16 g_en16[NE * EDIM];     // bf16 codebook (MMA B)
__device__ float g_e2[NE];                                    // ||en||^2
__device__ u64 g_cand[N_TOK * 8];                             // top-4 per token per half
__device__ int g_idx[N_TOK];
__device__ float g_loss_part[N_TOK];

__device__ __forceinline__ unsigned int fkey(float f) {
    unsigned int u = __float_as_uint(f);
    return u ^ ((unsigned int)((int)u >> 31) | 0x80000000u);
}
__device__ __forceinline__ uint32_t smem_u32(const void* p) {
    uint32_t a;
    asm("{ .reg .u64 t; cvta.to.shared.u64 t, %1; cvt.u32.u64 %0, t; }" : "=r"(a) : "l"(p));
    return a;
}
__device__ __forceinline__ void cp16(uint32_t dst, const void* src) {
    asm volatile("cp.async.cg.shared.global [%0], [%1], 16;" :: "r"(dst), "l"(src));
}
#define CP_COMMIT() asm volatile("cp.async.commit_group;" ::: "memory")
#define CP_WAIT0()  asm volatile("cp.async.wait_group 0;" ::: "memory")

__device__ __forceinline__ void ldm_x4(uint32_t* r, uint32_t addr) {
    asm volatile("ldmatrix.sync.aligned.m8n8.x4.shared.b16 {%0,%1,%2,%3}, [%4];"
                 : "=r"(r[0]), "=r"(r[1]), "=r"(r[2]), "=r"(r[3]) : "r"(addr));
}
__device__ __forceinline__ void mma16816(float* c, const uint32_t* a, uint32_t b0, uint32_t b1) {
    asm volatile(
        "mma.sync.aligned.m16n8k16.row.col.f32.bf16.bf16.f32 "
        "{%0,%1,%2,%3}, {%4,%5,%6,%7}, {%8,%9}, {%0,%1,%2,%3};"
        : "+f"(c[0]), "+f"(c[1]), "+f"(c[2]), "+f"(c[3])
        : "r"(a[0]), "r"(a[1]), "r"(a[2]), "r"(a[3]), "r"(b0), "r"(b1));
}
__device__ __forceinline__ void ins4(u64* t, u64 p) {
    if (p > t[0])      { t[3] = t[2]; t[2] = t[1]; t[1] = t[0]; t[0] = p; }
    else if (p > t[1]) { t[3] = t[2]; t[2] = t[1]; t[1] = p; }
    else if (p > t[2]) { t[3] = t[2]; t[2] = p; }
    else if (p > t[3]) { t[3] = p; }
}

// blocked-atom SW128 byte offset for (row, k) in a 128-row x 256-col bf16 tile
// atom = 8 rows x 64 bf16 (1024 B); atoms: (k/64)*16 + row/8
__device__ __forceinline__ uint32_t tile_off(int row, int k) {
    uint32_t byte = (uint32_t)(((k >> 6) * 16 + (row >> 3)) * 1024 + (row & 7) * 128 + (k & 63) * 2);
    return byte ^ ((byte >> 3) & 0x70);
}

// ---- smem layout for kscore (dynamic, 1024-aligned) ----
#define SM_A    0
#define SM_B0   65536
#define SM_B1   131072
#define SM_E0   196608
#define SM_E1   197120
#define SMEM_SZ 197632

// ---------------------------------------------------------------------------
// Kernel 1: normalize z tokens; emit fp32 + bf16.
__global__ void knorm_z(const float* __restrict__ z) {
    __shared__ float tile[32][EDIM + 1];
    int blk = blockIdx.x, b = blk >> 5, h = blk & 31, tid = threadIdx.x;
    const float* zb = z + (size_t)b * (EDIM * 1024) + h * 32;
    for (int i = tid; i < 32 * EDIM; i += 256) {
        int c = i >> 5, w = i & 31;
        tile[w][c] = zb[c * 1024 + w];
    }
    __syncthreads();
    int warp = tid >> 5, lane = tid & 31;
    for (int s = 0; s < 4; s++) {
        int w = warp * 4 + s;
        float acc = 0.f;
        #pragma unroll
        for (int c = lane; c < EDIM; c += 32) { float v = tile[w][c]; acc += v * v; }
        #pragma unroll
        for (int o = 16; o > 0; o >>= 1) acc += __shfl_xor_sync(0xFFFFFFFFu, acc, o);
        float den = fmaxf(sqrtf(acc), 1e-12f);
        int n = b * 1024 + h * 32 + w;
        #pragma unroll
        for (int c = lane; c < EDIM; c += 32) {
            float v = tile[w][c] / den;
            g_zn[(size_t)n * EDIM + c] = v;
            g_zn16[(size_t)n * EDIM + c] = __float2bfloat16_rn(v);
        }
    }
}

// ---------------------------------------------------------------------------
// Kernel 2: normalize codebook; emit fp32 + bf16 + e2.
__global__ void knorm_e(const float* __restrict__ emb) {
    int j = blockIdx.x, tid = threadIdx.x;
    float v = emb[(size_t)j * EDIM + tid];
    __shared__ float sm[8];
    float s = v * v;
    #pragma unroll
    for (int o = 16; o > 0; o >>= 1) s += __shfl_xor_sync(0xFFFFFFFFu, s, o);
    if ((tid & 31) == 0) sm[tid >> 5] = s;
    __syncthreads();
    float tot = sm[0] + sm[1] + sm[2] + sm[3] + sm[4] + sm[5] + sm[6] + sm[7];
    float den = fmaxf(sqrtf(tot), 1e-12f);
    float e = v / den;
    g_en[(size_t)j * EDIM + tid] = e;
    g_en16[(size_t)j * EDIM + tid] = __float2bfloat16_rn(e);
    __syncthreads();
    float s2 = e * e;
    #pragma unroll
    for (int o = 16; o > 0; o >>= 1) s2 += __shfl_xor_sync(0xFFFFFFFFu, s2, o);
    if ((tid & 31) == 0) sm[tid >> 5] = s2;
    __syncthreads();
    if (tid == 0)
        g_e2[j] = sm[0] + sm[1] + sm[2] + sm[3] + sm[4] + sm[5] + sm[6] + sm[7];
}

// ---------------------------------------------------------------------------
// Kernel 3: bf16 mma.sync scoring + per-token register top-4.
// grid (64 token-groups, 2 code-halves), 256 threads = 8 warps.
// Warp w owns token rows [16w, 16w+16) and computes all 128 cols per tile.
__global__ void __launch_bounds__(256, 1) kscore() {
    extern __shared__ __align__(1024) unsigned char smem[];
    uint32_t sb = smem_u32(smem);
    int tid = threadIdx.x, wid = tid >> 5, lane = tid & 31;
    int m0 = blockIdx.x * 128;
    int nbase = blockIdx.y * NHALF;

    // load A (resident), B tile 0, e2 tile 0
    {
        const __nv_bfloat16* A = g_zn16 + (size_t)m0 * EDIM;
        const __nv_bfloat16* B = g_en16 + (size_t)nbase * EDIM;
        for (int q = tid; q < 4096; q += 256) {
            int r = q >> 5, k = (q & 31) * 8;
            cp16(sb + SM_A  + tile_off(r, k), A + (size_t)r * EDIM + k);
            cp16(sb + SM_B0 + tile_off(r, k), B + (size_t)r * EDIM + k);
        }
        if (tid < 32) cp16(sb + SM_E0 + tid * 16, g_e2 + nbase + tid * 4);
    }
    CP_COMMIT(); CP_WAIT0();
    __syncthreads();

    int gr = lane >> 2, gc = lane & 3;
    int mw = wid * 16;
    int lm_row = (lane & 15);          // ldmatrix lane row within 16
    int lm_koff = (lane >> 4) * 8;     // ldmatrix lane k offset (0 or 8)

    u64 t0[4] = {0, 0, 0, 0};          // top-4 for row mw+gr
    u64 t1[4] = {0, 0, 0, 0};          // top-4 for row mw+gr+8

    for (int i = 0; i < NIT; i++) {
        int cur = i & 1;
        if (i + 1 < NIT) {             // prefetch next B + e2 into other buffer
            uint32_t bb = cur ? SM_B0 : SM_B1;
            uint32_t eb = cur ? SM_E0 : SM_E1;
            const __nv_bfloat16* B = g_en16 + (size_t)(nbase + (i + 1) * NTILE) * EDIM;
            for (int q = tid; q < 4096; q += 256) {
                int r = q >> 5, k = (q & 31) * 8;
                cp16(sb + bb + tile_off(r, k), B + (size_t)r * EDIM + k);
            }
            if (tid < 32) cp16(sb + eb + tid * 16, g_e2 + nbase + (i + 1) * NTILE + tid * 4);
            CP_COMMIT();
        }

        uint32_t Bb = sb + (cur ? SM_B1 : SM_B0);
        float acc[16][4];
        #pragma unroll
        for (int f = 0; f < 16; f++)
            #pragma unroll
            for (int c = 0; c < 4; c++) acc[f][c] = 0.f;

        #pragma unroll
        for (int ks = 0; ks < 16; ks++) {
            int k0 = ks * 16;
            uint32_t a[4];
            ldm_x4(a, sb + SM_A + tile_off(mw + lm_row, k0 + lm_koff));
            #pragma unroll
            for (int nf2 = 0; nf2 < 8; nf2++) {
                uint32_t b[4];
                ldm_x4(b, Bb + tile_off(nf2 * 16 + lm_row, k0 + lm_koff));
                // b[0]=n0..7@k0..7, b[1]=n8..15@k0..7, b[2]=n0..7@k8..15, b[3]=n8..15@k8..15
                mma16816(acc[nf2 * 2],     a, b[0], b[2]);
                mma16816(acc[nf2 * 2 + 1], a, b[1], b[3]);
            }
        }

        // epilogue: score = 2*acc - e2; insert into register top-4
        const float* e2s = (const float*)(smem + (cur ? SM_E1 : SM_E0));
        int ng = nbase + i * NTILE;
        #pragma unroll
        for (int nf = 0; nf < 16; nf++) {
            int nl = nf * 8 + gc * 2;
            float e0 = e2s[nl], e1 = e2s[nl + 1];
            float s00 = 2.0f * acc[nf][0] - e0, s01 = 2.0f * acc[nf][1] - e1;
            float s10 = 2.0f * acc[nf][2] - e0, s11 = 2.0f * acc[nf][3] - e1;
            ins4(t0, ((u64)fkey(s00) << 32) | (unsigned int)(~(unsigned int)(ng + nl)));
            ins4(t0, ((u64)fkey(s01) << 32) | (unsigned int)(~(unsigned int)(ng + nl + 1)));
            ins4(t1, ((u64)fkey(s10) << 32) | (unsigned int)(~(unsigned int)(ng + nl)));
            ins4(t1, ((u64)fkey(s11) << 32) | (unsigned int)(~(unsigned int)(ng + nl + 1)));
        }

        if (i + 1 < NIT) CP_WAIT0();
        __syncthreads();               // all reads of B_cur done; B_next visible
    }

    // quad merge (threads gc=0..3 share the same rows)
    #pragma unroll
    for (int off = 1; off <= 2; off <<= 1) {
        u64 in0[4], in1[4];
        #pragma unroll
        for (int s = 0; s < 4; s++) {
            in0[s] = __shfl_xor_sync(0xFFFFFFFFu, t0[s], off);
            in1[s] = __shfl_xor_sync(0xFFFFFFFFu, t1[s], off);
        }
        #pragma unroll
        for (int s = 0; s < 4; s++) { ins4(t0, in0[s]); ins4(t1, in1[s]); }
    }
    if (gc == 0) {
        size_t r0 = (size_t)(m0 + mw + gr) * 8 + blockIdx.y * 4;
        size_t r1 = (size_t)(m0 + mw + gr + 8) * 8 + blockIdx.y * 4;
        #pragma unroll
        for (int s = 0; s < 4; s++) { g_cand[r0 + s] = t0[s]; g_cand[r1 + s] = t1[s]; }
    }
}

// ---------------------------------------------------------------------------
// Kernel 4: exact fp64 rescore of 8 candidates; winner = argmin d (tie: smaller j).
__global__ void kpick8() {
    int tid = threadIdx.x, warp = tid >> 5, lane = tid & 31;
    int n = blockIdx.x * 8 + warp;
    const float* zr = g_zn + (size_t)n * EDIM;
    double bd = 0.0; int bj = -1;
    #pragma unroll
    for (int t = 0; t < 8; t++) {
        int j = (int)(~(unsigned int)g_cand[(size_t)n * 8 + t]);
        const float* er = g_en + (size_t)j * EDIM;
        double s = 0.0, q = 0.0;
        #pragma unroll
        for (int u = 0; u < 8; u++) {
            int c = lane * 8 + u;
            double a = (double)zr[c], x = (double)er[c];
            s += a * x; q += x * x;
        }
        #pragma unroll
        for (int o = 16; o > 0; o >>= 1) {
            s += __shfl_xor_sync(0xFFFFFFFFu, s, o);
            q += __shfl_xor_sync(0xFFFFFFFFu, q, o);
        }
        double d = q - 2.0 * s;
        if (bj < 0 || d < bd || (d == bd && j < bj)) { bd = d; bj = j; }
    }
    if (lane == 0) g_idx[n] = bj;
}

// ---------------------------------------------------------------------------
// Kernel 5: gather z_q = emb[idx] (raw weights), outputs, loss partials.
__global__ void kgather(const float* __restrict__ emb,
                        float* __restrict__ out_zq,
                        float* __restrict__ out_idx, int has_idx) {
    int n = blockIdx.x, c = threadIdx.x;
    int j = g_idx[n];
    float q = emb[(size_t)j * EDIM + c];
    float zv = g_zn[(size_t)n * EDIM + c];
    float d = q - zv;
    __shared__ float sm[8];
    float s = d * d;
    #pragma unroll
    for (int o = 16; o > 0; o >>= 1) s += __shfl_xor_sync(0xFFFFFFFFu, s, o);
    if ((c & 31) == 0) sm[c >> 5] = s;
    __syncthreads();
    if (c == 0)
        g_loss_part[n] = sm[0] + sm[1] + sm[2] + sm[3] + sm[4] + sm[5] + sm[6] + sm[7];
    int b = n >> 10, p2 = n & 1023;
    out_zq[(size_t)b * (EDIM * 1024) + (size_t)c * 1024 + p2] = q;
    if (c == 0 && has_idx) out_idx[n] = (float)j;
}

// ---------------------------------------------------------------------------
// Kernel 6: loss = 2.25 * mean(sq diff).
__global__ void kloss(float* __restrict__ out_loss) {
    int tid = threadIdx.x;
    double s = 0.0;
    for (int i = tid; i < N_TOK; i += 256) s += (double)g_loss_part[i];
    __shared__ double sm[8];
    #pragma unroll
    for (int o = 16; o > 0; o >>= 1) s += __shfl_xor_sync(0xFFFFFFFFu, s, o);
    if ((tid & 31) == 0) sm[tid >> 5] = s;
    __syncthreads();
    if (tid == 0) {
        double tot = sm[0] + sm[1] + sm[2] + sm[3] + sm[4] + sm[5] + sm[6] + sm[7];
        *out_loss = (float)(2.25 * tot / (double)((size_t)N_TOK * EDIM));
    }
}

// ---------------------------------------------------------------------------
extern "C" void kernel_launch(void* const* d_in, const int* in_sizes, int n_in,
                              void* d_out, int out_size) {
    const float* z   = (const float*)d_in[0];
    const float* emb = (const float*)d_in[n_in > 1 ? 1 : 0];
    for (int i = 0; i < n_in; i++) {
        long long sz = in_sizes[i];
        if (sz == Z_ELEMS)   z   = (const float*)d_in[i];
        if (sz == EMB_ELEMS) emb = (const float*)d_in[i];
    }

    float* out = (float*)d_out;
    float* out_zq = out;
    int has_idx  = out_size >= ZQ_ELEMS + N_TOK;
    int has_loss = out_size >= ZQ_ELEMS + N_TOK + 1;
    float* out_idx  = out + ZQ_ELEMS;
    float* out_loss = out + ZQ_ELEMS + N_TOK;

    static int smem_set = 0;
    if (!smem_set) {
        cudaFuncSetAttribute(kscore, cudaFuncAttributeMaxDynamicSharedMemorySize, SMEM_SZ);
        smem_set = 1;
    }

    knorm_z<<<256, 256>>>(z);
    knorm_e<<<NE, 256>>>(emb);
    kscore<<<dim3(64, 2), 256, SMEM_SZ>>>();
    kpick8<<<N_TOK / 8, 256>>>();
    kgather<<<N_TOK, 256>>>(emb, out_zq, has_idx ? out_idx : (float*)0, has_idx);
    if (has_loss) kloss<<<1, 256>>>(out_loss);
}

// round 12
// speedup vs baseline: 4.9208x; 1.7422x over previous
#include <cuda_runtime.h>
#include <cuda_bf16.h>
#include <stdint.h>

#define N_TOK 8192
#define NE    16384
#define EDIM  256
#define NTILE 128                    // codes per iteration
#define NHALF (NE / 2)               // codes per CTA (N-split by 2)
#define NIT   (NHALF / NTILE)        // 64 iterations
#define ZQ_ELEMS  (N_TOK * EDIM)     // 2,097,152
#define Z_ELEMS   (N_TOK * EDIM)
#define EMB_ELEMS (NE * EDIM)

typedef unsigned long long u64;

// ---- scratch (alloc-free: __device__ globals) ----
__device__ __align__(16) float g_zn[N_TOK * EDIM];            // fp32 normalized tokens
__device__ __align__(16) float g_en[NE * EDIM];               // fp32 normalized codebook
__device__ __align__(16) __nv_bfloat16 g_zn16[N_TOK * EDIM];  // bf16 tokens (MMA A)
__device__ __align__(16) __nv_bfloat16 g_en16[NE * EDIM];     // bf16 codebook (MMA B)
__device__ float g_e2[NE];                                    // ||en||^2
__device__ u64 g_cand[N_TOK * 8];                             // top-4 per token per half
__device__ int g_idx[N_TOK];
__device__ float g_loss_part[N_TOK];

__device__ __forceinline__ unsigned int fkey(float f) {
    unsigned int u = __float_as_uint(f);
    return u ^ ((unsigned int)((int)u >> 31) | 0x80000000u);
}
__device__ __forceinline__ uint32_t smem_u32(const void* p) {
    uint32_t a;
    asm("{ .reg .u64 t; cvta.to.shared.u64 t, %1; cvt.u32.u64 %0, t; }" : "=r"(a) : "l"(p));
    return a;
}
__device__ __forceinline__ void cp16(uint32_t dst, const void* src) {
    asm volatile("cp.async.cg.shared.global [%0], [%1], 16;" :: "r"(dst), "l"(src));
}
#define CP_COMMIT() asm volatile("cp.async.commit_group;" ::: "memory")
#define CP_WAIT0()  asm volatile("cp.async.wait_group 0;" ::: "memory")

__device__ __forceinline__ void ldm_x4(uint32_t* r, uint32_t addr) {
    asm volatile("ldmatrix.sync.aligned.m8n8.x4.shared.b16 {%0,%1,%2,%3}, [%4];"
                 : "=r"(r[0]), "=r"(r[1]), "=r"(r[2]), "=r"(r[3]) : "r"(addr));
}
__device__ __forceinline__ void mma16816(float* c, const uint32_t* a, uint32_t b0, uint32_t b1) {
    asm volatile(
        "mma.sync.aligned.m16n8k16.row.col.f32.bf16.bf16.f32 "
        "{%0,%1,%2,%3}, {%4,%5,%6,%7}, {%8,%9}, {%0,%1,%2,%3};"
        : "+f"(c[0]), "+f"(c[1]), "+f"(c[2]), "+f"(c[3])
        : "r"(a[0]), "r"(a[1]), "r"(a[2]), "r"(a[3]), "r"(b0), "r"(b1));
}
// cheap float-domain top-2 insert (strict >: first-seen wins ties -> deterministic)
__device__ __forceinline__ void ins2(float& a0, int& j0, float& a1, int& j1, float s, int j) {
    if (s > a1) {
        if (s > a0) { a1 = a0; j1 = j0; a0 = s; j0 = j; }
        else        { a1 = s;  j1 = j; }
    }
}
__device__ __forceinline__ void ins4u(u64* t, u64 p) {
    if (p > t[0])      { t[3] = t[2]; t[2] = t[1]; t[1] = t[0]; t[0] = p; }
    else if (p > t[1]) { t[3] = t[2]; t[2] = t[1]; t[1] = p; }
    else if (p > t[2]) { t[3] = t[2]; t[2] = p; }
    else if (p > t[3]) { t[3] = p; }
}

// blocked-atom SW128 byte offset for (row, k) in a 128-row x 256-col bf16 tile
__device__ __forceinline__ uint32_t tile_off(int row, int k) {
    uint32_t byte = (uint32_t)(((k >> 6) * 16 + (row >> 3)) * 1024 + (row & 7) * 128 + (k & 63) * 2);
    return byte ^ ((byte >> 3) & 0x70);
}

// ---- smem layout for kscore (dynamic, 1024-aligned) ----
#define SM_A    0
#define SM_B0   65536
#define SM_B1   131072
#define SM_E0   196608
#define SM_E1   197120
#define SMEM_SZ 197632

// ---------------------------------------------------------------------------
// Kernel 1: normalize z tokens; emit fp32 + bf16.
__global__ void knorm_z(const float* __restrict__ z) {
    __shared__ float tile[32][EDIM + 1];
    int blk = blockIdx.x, b = blk >> 5, h = blk & 31, tid = threadIdx.x;
    const float* zb = z + (size_t)b * (EDIM * 1024) + h * 32;
    for (int i = tid; i < 32 * EDIM; i += 256) {
        int c = i >> 5, w = i & 31;
        tile[w][c] = zb[c * 1024 + w];
    }
    __syncthreads();
    int warp = tid >> 5, lane = tid & 31;
    for (int s = 0; s < 4; s++) {
        int w = warp * 4 + s;
        float acc = 0.f;
        #pragma unroll
        for (int c = lane; c < EDIM; c += 32) { float v = tile[w][c]; acc += v * v; }
        #pragma unroll
        for (int o = 16; o > 0; o >>= 1) acc += __shfl_xor_sync(0xFFFFFFFFu, acc, o);
        float den = fmaxf(sqrtf(acc), 1e-12f);
        int n = b * 1024 + h * 32 + w;
        #pragma unroll
        for (int c = lane; c < EDIM; c += 32) {
            float v = tile[w][c] / den;
            g_zn[(size_t)n * EDIM + c] = v;
            g_zn16[(size_t)n * EDIM + c] = __float2bfloat16_rn(v);
        }
    }
}

// ---------------------------------------------------------------------------
// Kernel 2: normalize codebook; emit fp32 + bf16 + e2.
__global__ void knorm_e(const float* __restrict__ emb) {
    int j = blockIdx.x, tid = threadIdx.x;
    float v = emb[(size_t)j * EDIM + tid];
    __shared__ float sm[8];
    float s = v * v;
    #pragma unroll
    for (int o = 16; o > 0; o >>= 1) s += __shfl_xor_sync(0xFFFFFFFFu, s, o);
    if ((tid & 31) == 0) sm[tid >> 5] = s;
    __syncthreads();
    float tot = sm[0] + sm[1] + sm[2] + sm[3] + sm[4] + sm[5] + sm[6] + sm[7];
    float den = fmaxf(sqrtf(tot), 1e-12f);
    float e = v / den;
    g_en[(size_t)j * EDIM + tid] = e;
    g_en16[(size_t)j * EDIM + tid] = __float2bfloat16_rn(e);
    __syncthreads();
    float s2 = e * e;
    #pragma unroll
    for (int o = 16; o > 0; o >>= 1) s2 += __shfl_xor_sync(0xFFFFFFFFu, s2, o);
    if ((tid & 31) == 0) sm[tid >> 5] = s2;
    __syncthreads();
    if (tid == 0)
        g_e2[j] = sm[0] + sm[1] + sm[2] + sm[3] + sm[4] + sm[5] + sm[6] + sm[7];
}

// ---------------------------------------------------------------------------
// Kernel 3: bf16 mma.sync scoring; per-thread float top-2; end-merge to top-4/half.
__global__ void __launch_bounds__(256, 1) kscore() {
    extern __shared__ __align__(1024) unsigned char smem[];
    uint32_t sb = smem_u32(smem);
    int tid = threadIdx.x, wid = tid >> 5, lane = tid & 31;
    int m0 = blockIdx.x * 128;
    int nbase = blockIdx.y * NHALF;

    {
        const __nv_bfloat16* A = g_zn16 + (size_t)m0 * EDIM;
        const __nv_bfloat16* B = g_en16 + (size_t)nbase * EDIM;
        for (int q = tid; q < 4096; q += 256) {
            int r = q >> 5, k = (q & 31) * 8;
            cp16(sb + SM_A  + tile_off(r, k), A + (size_t)r * EDIM + k);
            cp16(sb + SM_B0 + tile_off(r, k), B + (size_t)r * EDIM + k);
        }
        if (tid < 32) cp16(sb + SM_E0 + tid * 16, g_e2 + nbase + tid * 4);
    }
    CP_COMMIT(); CP_WAIT0();
    __syncthreads();

    int gr = lane >> 2, gc = lane & 3;
    int mw = wid * 16;
    int lm_row = (lane & 15);
    int lm_koff = (lane >> 4) * 8;

    // per-thread float top-2 for each of my two token rows
    float a00 = -1e30f, a01 = -1e30f, a10 = -1e30f, a11 = -1e30f;
    int   j00 = 0,      j01 = 0,      j10 = 0,      j11 = 0;

    for (int i = 0; i < NIT; i++) {
        int cur = i & 1;
        if (i + 1 < NIT) {
            uint32_t bb = cur ? SM_B0 : SM_B1;
            uint32_t eb = cur ? SM_E0 : SM_E1;
            const __nv_bfloat16* B = g_en16 + (size_t)(nbase + (i + 1) * NTILE) * EDIM;
            for (int q = tid; q < 4096; q += 256) {
                int r = q >> 5, k = (q & 31) * 8;
                cp16(sb + bb + tile_off(r, k), B + (size_t)r * EDIM + k);
            }
            if (tid < 32) cp16(sb + eb + tid * 16, g_e2 + nbase + (i + 1) * NTILE + tid * 4);
            CP_COMMIT();
        }

        uint32_t Bb = sb + (cur ? SM_B1 : SM_B0);
        float acc[16][4];
        #pragma unroll
        for (int f = 0; f < 16; f++)
            #pragma unroll
            for (int c = 0; c < 4; c++) acc[f][c] = 0.f;

        #pragma unroll
        for (int ks = 0; ks < 16; ks++) {
            int k0 = ks * 16;
            uint32_t a[4];
            ldm_x4(a, sb + SM_A + tile_off(mw + lm_row, k0 + lm_koff));
            uint32_t bcur[4];
            ldm_x4(bcur, Bb + tile_off(lm_row, k0 + lm_koff));        // nf2 = 0
            #pragma unroll
            for (int nf2 = 0; nf2 < 8; nf2++) {
                uint32_t bnxt[4];
                if (nf2 < 7)
                    ldm_x4(bnxt, Bb + tile_off((nf2 + 1) * 16 + lm_row, k0 + lm_koff));
                mma16816(acc[nf2 * 2],     a, bcur[0], bcur[2]);
                mma16816(acc[nf2 * 2 + 1], a, bcur[1], bcur[3]);
                if (nf2 < 7) {
                    bcur[0] = bnxt[0]; bcur[1] = bnxt[1];
                    bcur[2] = bnxt[2]; bcur[3] = bnxt[3];
                }
            }
        }

        const float* e2s = (const float*)(smem + (cur ? SM_E1 : SM_E0));
        int ng = nbase + i * NTILE;
        #pragma unroll
        for (int nf = 0; nf < 16; nf++) {
            int nl = nf * 8 + gc * 2;
            float e0 = e2s[nl], e1 = e2s[nl + 1];
            float s00 = 2.0f * acc[nf][0] - e0, s01 = 2.0f * acc[nf][1] - e1;
            float s10 = 2.0f * acc[nf][2] - e0, s11 = 2.0f * acc[nf][3] - e1;
            ins2(a00, j00, a01, j01, s00, ng + nl);
            ins2(a00, j00, a01, j01, s01, ng + nl + 1);
            ins2(a10, j10, a11, j11, s10, ng + nl);
            ins2(a10, j10, a11, j11, s11, ng + nl + 1);
        }

        if (i + 1 < NIT) CP_WAIT0();
        __syncthreads();
    }

    // pack once, quad-merge (lanes gc=0..3 share rows) to top-4 per row per half
    u64 q0[4], q1[4];
    q0[0] = ((u64)fkey(a00) << 32) | (unsigned int)(~(unsigned int)j00);
    q0[1] = ((u64)fkey(a01) << 32) | (unsigned int)(~(unsigned int)j01);
    q0[2] = 0; q0[3] = 0;
    q1[0] = ((u64)fkey(a10) << 32) | (unsigned int)(~(unsigned int)j10);
    q1[1] = ((u64)fkey(a11) << 32) | (unsigned int)(~(unsigned int)j11);
    q1[2] = 0; q1[3] = 0;
    #pragma unroll
    for (int off = 1; off <= 2; off <<= 1) {
        u64 in0[4], in1[4];
        #pragma unroll
        for (int s = 0; s < 4; s++) {
            in0[s] = __shfl_xor_sync(0xFFFFFFFFu, q0[s], off);
            in1[s] = __shfl_xor_sync(0xFFFFFFFFu, q1[s], off);
        }
        #pragma unroll
        for (int s = 0; s < 4; s++) { ins4u(q0, in0[s]); ins4u(q1, in1[s]); }
    }
    if (gc == 0) {
        size_t r0 = (size_t)(m0 + mw + gr) * 8 + blockIdx.y * 4;
        size_t r1 = (size_t)(m0 + mw + gr + 8) * 8 + blockIdx.y * 4;
        #pragma unroll
        for (int s = 0; s < 4; s++) { g_cand[r0 + s] = q0[s]; g_cand[r1 + s] = q1[s]; }
    }
}

// ---------------------------------------------------------------------------
// Kernel 4: exact fp64 rescore of 8 candidates; winner = argmin d (tie: smaller j).
__global__ void kpick8() {
    int tid = threadIdx.x, warp = tid >> 5, lane = tid & 31;
    int n = blockIdx.x * 8 + warp;
    const float* zr = g_zn + (size_t)n * EDIM;
    double bd = 0.0; int bj = -1;
    #pragma unroll
    for (int t = 0; t < 8; t++) {
        int j = (int)(~(unsigned int)g_cand[(size_t)n * 8 + t]);
        const float* er = g_en + (size_t)j * EDIM;
        double s = 0.0, q = 0.0;
        #pragma unroll
        for (int u = 0; u < 8; u++) {
            int c = lane * 8 + u;
            double a = (double)zr[c], x = (double)er[c];
            s += a * x; q += x * x;
        }
        #pragma unroll
        for (int o = 16; o > 0; o >>= 1) {
            s += __shfl_xor_sync(0xFFFFFFFFu, s, o);
            q += __shfl_xor_sync(0xFFFFFFFFu, q, o);
        }
        double d = q - 2.0 * s;
        if (bj < 0 || d < bd || (d == bd && j < bj)) { bd = d; bj = j; }
    }
    if (lane == 0) g_idx[n] = bj;
}

// ---------------------------------------------------------------------------
// Kernel 5: gather z_q = emb[idx] (raw weights), outputs, loss partials.
__global__ void kgather(const float* __restrict__ emb,
                        float* __restrict__ out_zq,
                        float* __restrict__ out_idx, int has_idx) {
    int n = blockIdx.x, c = threadIdx.x;
    int j = g_idx[n];
    float q = emb[(size_t)j * EDIM + c];
    float zv = g_zn[(size_t)n * EDIM + c];
    float d = q - zv;
    __shared__ float sm[8];
    float s = d * d;
    #pragma unroll
    for (int o = 16; o > 0; o >>= 1) s += __shfl_xor_sync(0xFFFFFFFFu, s, o);
    if ((c & 31) == 0) sm[c >> 5] = s;
    __syncthreads();
    if (c == 0)
        g_loss_part[n] = sm[0] + sm[1] + sm[2] + sm[3] + sm[4] + sm[5] + sm[6] + sm[7];
    int b = n >> 10, p2 = n & 1023;
    out_zq[(size_t)b * (EDIM * 1024) + (size_t)c * 1024 + p2] = q;
    if (c == 0 && has_idx) out_idx[n] = (float)j;
}

// ---------------------------------------------------------------------------
// Kernel 6: loss = 2.25 * mean(sq diff).
__global__ void kloss(float* __restrict__ out_loss) {
    int tid = threadIdx.x;
    double s = 0.0;
    for (int i = tid; i < N_TOK; i += 256) s += (double)g_loss_part[i];
    __shared__ double sm[8];
    #pragma unroll
    for (int o = 16; o > 0; o >>= 1) s += __shfl_xor_sync(0xFFFFFFFFu, s, o);
    if ((tid & 31) == 0) sm[tid >> 5] = s;
    __syncthreads();
    if (tid == 0) {
        double tot = sm[0] + sm[1] + sm[2] + sm[3] + sm[4] + sm[5] + sm[6] + sm[7];
        *out_loss = (float)(2.25 * tot / (double)((size_t)N_TOK * EDIM));
    }
}

// ---------------------------------------------------------------------------
extern "C" void kernel_launch(void* const* d_in, const int* in_sizes, int n_in,
                              void* d_out, int out_size) {
    const float* z   = (const float*)d_in[0];
    const float* emb = (const float*)d_in[n_in > 1 ? 1 : 0];
    for (int i = 0; i < n_in; i++) {
        long long sz = in_sizes[i];
        if (sz == Z_ELEMS)   z   = (const float*)d_in[i];
        if (sz == EMB_ELEMS) emb = (const float*)d_in[i];
    }

    float* out = (float*)d_out;
    float* out_zq = out;
    int has_idx  = out_size >= ZQ_ELEMS + N_TOK;
    int has_loss = out_size >= ZQ_ELEMS + N_TOK + 1;
    float* out_idx  = out + ZQ_ELEMS;
    float* out_loss = out + ZQ_ELEMS + N_TOK;

    static int smem_set = 0;
    if (!smem_set) {
        cudaFuncSetAttribute(kscore, cudaFuncAttributeMaxDynamicSharedMemorySize, SMEM_SZ);
        smem_set = 1;
    }

    knorm_z<<<256, 256>>>(z);
    knorm_e<<<NE, 256>>>(emb);
    kscore<<<dim3(64, 2), 256, SMEM_SZ>>>();
    kpick8<<<N_TOK / 8, 256>>>();
    kgather<<<N_TOK, 256>>>(emb, out_zq, has_idx ? out_idx : (float*)0, has_idx);
    if (has_loss) kloss<<<1, 256>>>(out_loss);
}

// round 14
// speedup vs baseline: 6.6303x; 1.3474x over previous
#include <cuda_runtime.h>
#include <cuda_bf16.h>
#include <stdint.h>

#define N_TOK 8192
#define NE    16384
#define EDIM  256
#define NTILE 128                    // codes per iteration
#define NHALF (NE / 2)               // codes per CTA (N-split by 2)
#define NIT   (NHALF / NTILE)        // 64 iterations
#define ZQ_ELEMS  (N_TOK * EDIM)     // 2,097,152
#define Z_ELEMS   (N_TOK * EDIM)
#define EMB_ELEMS (NE * EDIM)

typedef unsigned long long u64;

// ---- scratch (alloc-free: __device__ globals) ----
__device__ __align__(16) float g_zn[N_TOK * EDIM];       // fp32 normalized tokens
__device__ __align__(16) float g_en[NE * EDIM];          // fp32 normalized codebook
__device__ __align__(16) int8_t g_zn8[N_TOK * EDIM];     // int8 tokens (MMA A)
__device__ __align__(16) int8_t g_en8[NE * EDIM];        // int8 codebook (MMA B)
__device__ float g_e2[NE];                               // ||en||^2
__device__ float g_sz[N_TOK];                            // token dequant scale (incl. factor 2)
__device__ float g_se[NE];                               // code dequant scale
__device__ u64 g_cand[N_TOK * 8];                        // top-4 per token per half
__device__ int g_idx[N_TOK];
__device__ float g_loss_part[N_TOK];

__device__ __forceinline__ unsigned int fkey(float f) {
    unsigned int u = __float_as_uint(f);
    return u ^ ((unsigned int)((int)u >> 31) | 0x80000000u);
}
__device__ __forceinline__ uint32_t smem_u32(const void* p) {
    uint32_t a;
    asm("{ .reg .u64 t; cvta.to.shared.u64 t, %1; cvt.u32.u64 %0, t; }" : "=r"(a) : "l"(p));
    return a;
}
__device__ __forceinline__ void cp16(uint32_t dst, const void* src) {
    asm volatile("cp.async.cg.shared.global [%0], [%1], 16;" :: "r"(dst), "l"(src));
}
#define CP_COMMIT() asm volatile("cp.async.commit_group;" ::: "memory")
#define CP_WAIT0()  asm volatile("cp.async.wait_group 0;" ::: "memory")

__device__ __forceinline__ void ldm_x4(uint32_t* r, uint32_t addr) {
    asm volatile("ldmatrix.sync.aligned.m8n8.x4.shared.b16 {%0,%1,%2,%3}, [%4];"
                 : "=r"(r[0]), "=r"(r[1]), "=r"(r[2]), "=r"(r[3]) : "r"(addr));
}
// int8 MMA: D(s32) += A(s8,16x32) * B(s8,32x8)
__device__ __forceinline__ void mma16832(int* c, const uint32_t* a, uint32_t b0, uint32_t b1) {
    asm volatile(
        "mma.sync.aligned.m16n8k32.row.col.s32.s8.s8.s32 "
        "{%0,%1,%2,%3}, {%4,%5,%6,%7}, {%8,%9}, {%0,%1,%2,%3};"
        : "+r"(c[0]), "+r"(c[1]), "+r"(c[2]), "+r"(c[3])
        : "r"(a[0]), "r"(a[1]), "r"(a[2]), "r"(a[3]), "r"(b0), "r"(b1));
}
__device__ __forceinline__ void ins2(float& a0, int& j0, float& a1, int& j1, float s, int j) {
    if (s > a1) {
        if (s > a0) { a1 = a0; j1 = j0; a0 = s; j0 = j; }
        else        { a1 = s;  j1 = j; }
    }
}
__device__ __forceinline__ void ins4u(u64* t, u64 p) {
    if (p > t[0])      { t[3] = t[2]; t[2] = t[1]; t[1] = t[0]; t[0] = p; }
    else if (p > t[1]) { t[3] = t[2]; t[2] = t[1]; t[1] = p; }
    else if (p > t[2]) { t[3] = t[2]; t[2] = p; }
    else if (p > t[3]) { t[3] = p; }
}
__device__ __forceinline__ int8_t qscale(float v, float inv) {
    int q = __float2int_rn(v * inv);
    q = (q > 127) ? 127 : ((q < -127) ? -127 : q);
    return (int8_t)q;
}

// blocked-atom SW128 byte offset for (row, kbyte) in a 128-row x 256-byte int8 tile
__device__ __forceinline__ uint32_t tile_off(int row, int kbyte) {
    uint32_t byte = (uint32_t)(((kbyte >> 7) * 16 + (row >> 3)) * 1024 + (row & 7) * 128 + (kbyte & 127));
    return byte ^ ((byte >> 3) & 0x70);
}

// ---- smem layout for kscore (dynamic, 1024-aligned) ----
// E buffer: e2[128] floats (512 B) then se[128] floats (512 B)
#define SM_A    0
#define SM_B0   32768
#define SM_B1   65536
#define SM_E0   98304
#define SM_E1   99328
#define SMEM_SZ 100352

// ---------------------------------------------------------------------------
// Kernel 1: normalize z tokens; emit fp32 + per-row-scaled int8.
__global__ void knorm_z(const float* __restrict__ z) {
    __shared__ float tile[32][EDIM + 1];
    int blk = blockIdx.x, b = blk >> 5, h = blk & 31, tid = threadIdx.x;
    const float* zb = z + (size_t)b * (EDIM * 1024) + h * 32;
    for (int i = tid; i < 32 * EDIM; i += 256) {
        int c = i >> 5, w = i & 31;
        tile[w][c] = zb[c * 1024 + w];
    }
    __syncthreads();
    int warp = tid >> 5, lane = tid & 31;
    for (int s = 0; s < 4; s++) {
        int w = warp * 4 + s;
        float acc = 0.f, mx = 0.f;
        #pragma unroll
        for (int c = lane; c < EDIM; c += 32) {
            float v = tile[w][c];
            acc += v * v;
            mx = fmaxf(mx, fabsf(v));
        }
        #pragma unroll
        for (int o = 16; o > 0; o >>= 1) {
            acc += __shfl_xor_sync(0xFFFFFFFFu, acc, o);
            mx = fmaxf(mx, __shfl_xor_sync(0xFFFFFFFFu, mx, o));
        }
        float den = fmaxf(sqrtf(acc), 1e-12f);
        float mxn = fmaxf(mx / den, 1e-12f);          // max|normalized row|
        float inv = 127.0f / mxn;
        int n = b * 1024 + h * 32 + w;
        if (lane == 0) g_sz[n] = 2.0f * mxn / 127.0f; // includes factor 2 of the score
        #pragma unroll
        for (int c = lane; c < EDIM; c += 32) {
            float v = tile[w][c] / den;
            g_zn[(size_t)n * EDIM + c] = v;
            g_zn8[(size_t)n * EDIM + c] = qscale(v, inv);
        }
    }
}

// ---------------------------------------------------------------------------
// Kernel 2: normalize codebook; emit fp32 + per-row-scaled int8 + e2 + se.
__global__ void knorm_e(const float* __restrict__ emb) {
    int j = blockIdx.x, tid = threadIdx.x;
    float v = emb[(size_t)j * EDIM + tid];
    __shared__ float sm[8], sx[8];
    float s = v * v;
    #pragma unroll
    for (int o = 16; o > 0; o >>= 1) s += __shfl_xor_sync(0xFFFFFFFFu, s, o);
    if ((tid & 31) == 0) sm[tid >> 5] = s;
    __syncthreads();
    float tot = sm[0] + sm[1] + sm[2] + sm[3] + sm[4] + sm[5] + sm[6] + sm[7];
    float den = fmaxf(sqrtf(tot), 1e-12f);
    float e = v / den;
    g_en[(size_t)j * EDIM + tid] = e;
    // row max of |e|
    float mx = fabsf(e);
    #pragma unroll
    for (int o = 16; o > 0; o >>= 1) mx = fmaxf(mx, __shfl_xor_sync(0xFFFFFFFFu, mx, o));
    if ((tid & 31) == 0) sx[tid >> 5] = mx;
    __syncthreads();
    float mxr = fmaxf(fmaxf(fmaxf(sx[0], sx[1]), fmaxf(sx[2], sx[3])),
                      fmaxf(fmaxf(sx[4], sx[5]), fmaxf(sx[6], sx[7])));
    mxr = fmaxf(mxr, 1e-12f);
    g_en8[(size_t)j * EDIM + tid] = qscale(e, 127.0f / mxr);
    float s2 = e * e;
    #pragma unroll
    for (int o = 16; o > 0; o >>= 1) s2 += __shfl_xor_sync(0xFFFFFFFFu, s2, o);
    if ((tid & 31) == 0) sm[tid >> 5] = s2;
    __syncthreads();
    if (tid == 0) {
        g_e2[j] = sm[0] + sm[1] + sm[2] + sm[3] + sm[4] + sm[5] + sm[6] + sm[7];
        g_se[j] = mxr / 127.0f;
    }
}

// ---------------------------------------------------------------------------
// Kernel 3: int8 IMMA scoring; per-thread float top-2; end-merge to top-4/half.
__global__ void __launch_bounds__(256, 1) kscore() {
    extern __shared__ __align__(1024) unsigned char smem[];
    uint32_t sb = smem_u32(smem);
    int tid = threadIdx.x, wid = tid >> 5, lane = tid & 31;
    int m0 = blockIdx.x * 128;
    int nbase = blockIdx.y * NHALF;

    {
        const int8_t* A = g_zn8 + (size_t)m0 * EDIM;
        const int8_t* B = g_en8 + (size_t)nbase * EDIM;
        for (int q = tid; q < 2048; q += 256) {
            int r = q >> 4, kb = (q & 15) * 16;
            cp16(sb + SM_A  + tile_off(r, kb), A + (size_t)r * EDIM + kb);
            cp16(sb + SM_B0 + tile_off(r, kb), B + (size_t)r * EDIM + kb);
        }
        if (tid < 32)       cp16(sb + SM_E0 + tid * 16, g_e2 + nbase + tid * 4);
        else if (tid < 64)  cp16(sb + SM_E0 + 512 + (tid - 32) * 16, g_se + nbase + (tid - 32) * 4);
    }
    CP_COMMIT(); CP_WAIT0();
    __syncthreads();

    int gr = lane >> 2, gc = lane & 3;
    int mw = wid * 16;
    int lm_row = (lane & 15);
    int lm_koff = (lane >> 4) * 16;        // bytes

    float szr0 = g_sz[m0 + mw + gr];       // row mw+gr   (includes the 2x)
    float szr1 = g_sz[m0 + mw + gr + 8];   // row mw+gr+8

    float a00 = -1e30f, a01 = -1e30f, a10 = -1e30f, a11 = -1e30f;
    int   j00 = 0,      j01 = 0,      j10 = 0,      j11 = 0;

    for (int i = 0; i < NIT; i++) {
        int cur = i & 1;
        if (i + 1 < NIT) {
            uint32_t bb = cur ? SM_B0 : SM_B1;
            uint32_t eb = cur ? SM_E0 : SM_E1;
            const int8_t* B = g_en8 + (size_t)(nbase + (i + 1) * NTILE) * EDIM;
            for (int q = tid; q < 2048; q += 256) {
                int r = q >> 4, kb = (q & 15) * 16;
                cp16(sb + bb + tile_off(r, kb), B + (size_t)r * EDIM + kb);
            }
            if (tid < 32)      cp16(sb + eb + tid * 16, g_e2 + nbase + (i + 1) * NTILE + tid * 4);
            else if (tid < 64) cp16(sb + eb + 512 + (tid - 32) * 16,
                                    g_se + nbase + (i + 1) * NTILE + (tid - 32) * 4);
            CP_COMMIT();
        }

        uint32_t Bb = sb + (cur ? SM_B1 : SM_B0);
        int acc[16][4];
        #pragma unroll
        for (int f = 0; f < 16; f++)
            #pragma unroll
            for (int c = 0; c < 4; c++) acc[f][c] = 0;

        #pragma unroll
        for (int ks = 0; ks < 8; ks++) {           // 8 x 32-byte k-steps = 256
            int k0 = ks * 32;
            uint32_t a[4];
            ldm_x4(a, sb + SM_A + tile_off(mw + lm_row, k0 + lm_koff));
            uint32_t bcur[4];
            ldm_x4(bcur, Bb + tile_off(lm_row, k0 + lm_koff));   // nf2 = 0
            #pragma unroll
            for (int nf2 = 0; nf2 < 8; nf2++) {
                uint32_t bnxt[4];
                if (nf2 < 7)
                    ldm_x4(bnxt, Bb + tile_off((nf2 + 1) * 16 + lm_row, k0 + lm_koff));
                mma16832(acc[nf2 * 2],     a, bcur[0], bcur[2]);
                mma16832(acc[nf2 * 2 + 1], a, bcur[1], bcur[3]);
                if (nf2 < 7) {
                    bcur[0] = bnxt[0]; bcur[1] = bnxt[1];
                    bcur[2] = bnxt[2]; bcur[3] = bnxt[3];
                }
            }
        }

        const float* e2s = (const float*)(smem + (cur ? SM_E1 : SM_E0));
        const float* ses = e2s + 128;
        int ng = nbase + i * NTILE;
        #pragma unroll
        for (int nf = 0; nf < 16; nf++) {
            int nl = nf * 8 + gc * 2;
            float e0 = e2s[nl], e1 = e2s[nl + 1];
            float f0 = ses[nl], f1 = ses[nl + 1];
            float s00 = (float)acc[nf][0] * (szr0 * f0) - e0;
            float s01 = (float)acc[nf][1] * (szr0 * f1) - e1;
            float s10 = (float)acc[nf][2] * (szr1 * f0) - e0;
            float s11 = (float)acc[nf][3] * (szr1 * f1) - e1;
            ins2(a00, j00, a01, j01, s00, ng + nl);
            ins2(a00, j00, a01, j01, s01, ng + nl + 1);
            ins2(a10, j10, a11, j11, s10, ng + nl);
            ins2(a10, j10, a11, j11, s11, ng + nl + 1);
        }

        if (i + 1 < NIT) CP_WAIT0();
        __syncthreads();
    }

    // pack once, quad-merge (lanes gc=0..3 share rows) to top-4 per row per half
    u64 q0[4], q1[4];
    q0[0] = ((u64)fkey(a00) << 32) | (unsigned int)(~(unsigned int)j00);
    q0[1] = ((u64)fkey(a01) << 32) | (unsigned int)(~(unsigned int)j01);
    q0[2] = 0; q0[3] = 0;
    q1[0] = ((u64)fkey(a10) << 32) | (unsigned int)(~(unsigned int)j10);
    q1[1] = ((u64)fkey(a11) << 32) | (unsigned int)(~(unsigned int)j11);
    q1[2] = 0; q1[3] = 0;
    #pragma unroll
    for (int off = 1; off <= 2; off <<= 1) {
        u64 in0[4], in1[4];
        #pragma unroll
        for (int s = 0; s < 4; s++) {
            in0[s] = __shfl_xor_sync(0xFFFFFFFFu, q0[s], off);
            in1[s] = __shfl_xor_sync(0xFFFFFFFFu, q1[s], off);
        }
        #pragma unroll
        for (int s = 0; s < 4; s++) { ins4u(q0, in0[s]); ins4u(q1, in1[s]); }
    }
    if (gc == 0) {
        size_t r0 = (size_t)(m0 + mw + gr) * 8 + blockIdx.y * 4;
        size_t r1 = (size_t)(m0 + mw + gr + 8) * 8 + blockIdx.y * 4;
        #pragma unroll
        for (int s = 0; s < 4; s++) { g_cand[r0 + s] = q0[s]; g_cand[r1 + s] = q1[s]; }
    }
}

// ---------------------------------------------------------------------------
// Kernel 4: exact fp64 rescore of 8 candidates; winner = argmin d (tie: smaller j).
__global__ void kpick8() {
    int tid = threadIdx.x, warp = tid >> 5, lane = tid & 31;
    int n = blockIdx.x * 8 + warp;
    const float* zr = g_zn + (size_t)n * EDIM;
    double bd = 0.0; int bj = -1;
    #pragma unroll
    for (int t = 0; t < 8; t++) {
        int j = (int)(~(unsigned int)g_cand[(size_t)n * 8 + t]);
        const float* er = g_en + (size_t)j * EDIM;
        double s = 0.0, q = 0.0;
        #pragma unroll
        for (int u = 0; u < 8; u++) {
            int c = lane * 8 + u;
            double a = (double)zr[c], x = (double)er[c];
            s += a * x; q += x * x;
        }
        #pragma unroll
        for (int o = 16; o > 0; o >>= 1) {
            s += __shfl_xor_sync(0xFFFFFFFFu, s, o);
            q += __shfl_xor_sync(0xFFFFFFFFu, q, o);
        }
        double d = q - 2.0 * s;
        if (bj < 0 || d < bd || (d == bd && j < bj)) { bd = d; bj = j; }
    }
    if (lane == 0) g_idx[n] = bj;
}

// ---------------------------------------------------------------------------
// Kernel 5: gather z_q = emb[idx] (raw weights), outputs, loss partials.
__global__ void kgather(const float* __restrict__ emb,
                        float* __restrict__ out_zq,
                        float* __restrict__ out_idx, int has_idx) {
    int n = blockIdx.x, c = threadIdx.x;
    int j = g_idx[n];
    float q = emb[(size_t)j * EDIM + c];
    float zv = g_zn[(size_t)n * EDIM + c];
    float d = q - zv;
    __shared__ float sm[8];
    float s = d * d;
    #pragma unroll
    for (int o = 16; o > 0; o >>= 1) s += __shfl_xor_sync(0xFFFFFFFFu, s, o);
    if ((c & 31) == 0) sm[c >> 5] = s;
    __syncthreads();
    if (c == 0)
        g_loss_part[n] = sm[0] + sm[1] + sm[2] + sm[3] + sm[4] + sm[5] + sm[6] + sm[7];
    int b = n >> 10, p2 = n & 1023;
    out_zq[(size_t)b * (EDIM * 1024) + (size_t)c * 1024 + p2] = q;
    if (c == 0 && has_idx) out_idx[n] = (float)j;
}

// ---------------------------------------------------------------------------
// Kernel 6: loss = 2.25 * mean(sq diff).
__global__ void kloss(float* __restrict__ out_loss) {
    int tid = threadIdx.x;
    double s = 0.0;
    for (int i = tid; i < N_TOK; i += 256) s += (double)g_loss_part[i];
    __shared__ double sm[8];
    #pragma unroll
    for (int o = 16; o > 0; o >>= 1) s += __shfl_xor_sync(0xFFFFFFFFu, s, o);
    if ((tid & 31) == 0) sm[tid >> 5] = s;
    __syncthreads();
    if (tid == 0) {
        double tot = sm[0] + sm[1] + sm[2] + sm[3] + sm[4] + sm[5] + sm[6] + sm[7];
        *out_loss = (float)(2.25 * tot / (double)((size_t)N_TOK * EDIM));
    }
}

// ---------------------------------------------------------------------------
extern "C" void kernel_launch(void* const* d_in, const int* in_sizes, int n_in,
                              void* d_out, int out_size) {
    const float* z   = (const float*)d_in[0];
    const float* emb = (const float*)d_in[n_in > 1 ? 1 : 0];
    for (int i = 0; i < n_in; i++) {
        long long sz = in_sizes[i];
        if (sz == Z_ELEMS)   z   = (const float*)d_in[i];
        if (sz == EMB_ELEMS) emb = (const float*)d_in[i];
    }

    float* out = (float*)d_out;
    float* out_zq = out;
    int has_idx  = out_size >= ZQ_ELEMS + N_TOK;
    int has_loss = out_size >= ZQ_ELEMS + N_TOK + 1;
    float* out_idx  = out + ZQ_ELEMS;
    float* out_loss = out + ZQ_ELEMS + N_TOK;

    static int smem_set = 0;
    if (!smem_set) {
        cudaFuncSetAttribute(kscore, cudaFuncAttributeMaxDynamicSharedMemorySize, SMEM_SZ);
        smem_set = 1;
    }

    knorm_z<<<256, 256>>>(z);
    knorm_e<<<NE, 256>>>(emb);
    kscore<<<dim3(64, 2), 256, SMEM_SZ>>>();
    kpick8<<<N_TOK / 8, 256>>>();
    kgather<<<N_TOK, 256>>>(emb, out_zq, has_idx ? out_idx : (float*)0, has_idx);
    if (has_loss) kloss<<<1, 256>>>(out_loss);
}